// round 2
// baseline (speedup 1.0000x reference)
#include <cuda_runtime.h>
#include <math.h>

#define NN 4096
#define DD 256
#define BM 64

// ---------------- scratch (device globals; no allocations allowed) ----------
__device__ float g_Wh[3][NN * DD];     // 12 MB
__device__ float g_src[3][NN];
__device__ float g_dst[3][NN];
__device__ float g_out3[3][NN * DD];   // 12 MB partial outputs

// ---------------------------------------------------------------------------
// Kernel 1: Wh_r = H @ W_r^T.  BM=32 rows, BN=256 (all cols), BK=32.
// 256 threads, each computes a 4x8 micro-tile.  Small kernel (~0.8 G FMA).
// ---------------------------------------------------------------------------
__global__ void __launch_bounds__(256) wh_gemm_kernel(
    const float* __restrict__ H,
    const float* __restrict__ W1, const float* __restrict__ W2,
    const float* __restrict__ W3)
{
    const int r = blockIdx.y;
    const float* __restrict__ W = (r == 0) ? W1 : ((r == 1) ? W2 : W3);
    const int i0 = blockIdx.x * 32;

    __shared__ float Hs[32][32];    // [i][k]
    __shared__ float Ws[32][256];   // [k][d]  (transposed on load)

    const int tid = threadIdx.x;
    const int ty = tid >> 5;   // 0..7  -> row group (4 rows)
    const int tx = tid & 31;   // 0..31 -> col group (8 cols, split 4+4)

    float acc[4][8];
#pragma unroll
    for (int a = 0; a < 4; a++)
#pragma unroll
        for (int b = 0; b < 8; b++) acc[a][b] = 0.f;

    for (int k0 = 0; k0 < DD; k0 += 32) {
        {
            int row = tid >> 3;        // 0..31
            int q   = tid & 7;         // 0..7
            float4 v = *(const float4*)(H + (size_t)(i0 + row) * DD + k0 + q * 4);
            Hs[row][q * 4 + 0] = v.x; Hs[row][q * 4 + 1] = v.y;
            Hs[row][q * 4 + 2] = v.z; Hs[row][q * 4 + 3] = v.w;
        }
        {
            const float* wp = W + (size_t)tid * DD + k0;
#pragma unroll
            for (int q = 0; q < 8; q++) {
                float4 v = *(const float4*)(wp + q * 4);
                Ws[q * 4 + 0][tid] = v.x; Ws[q * 4 + 1][tid] = v.y;
                Ws[q * 4 + 2][tid] = v.z; Ws[q * 4 + 3][tid] = v.w;
            }
        }
        __syncthreads();

#pragma unroll
        for (int kk = 0; kk < 32; kk++) {
            float bv[8];
            *(float4*)&bv[0] = *(const float4*)&Ws[kk][tx * 4];
            *(float4*)&bv[4] = *(const float4*)&Ws[kk][128 + tx * 4];
#pragma unroll
            for (int a = 0; a < 4; a++) {
                float av = Hs[ty * 4 + a][kk];   // warp broadcast
#pragma unroll
                for (int b = 0; b < 8; b++) acc[a][b] += av * bv[b];
            }
        }
        __syncthreads();
    }

    float* out = g_Wh[r];
#pragma unroll
    for (int a = 0; a < 4; a++) {
        int i = i0 + ty * 4 + a;
        *(float4*)&out[(size_t)i * DD + tx * 4] =
            make_float4(acc[a][0], acc[a][1], acc[a][2], acc[a][3]);
        *(float4*)&out[(size_t)i * DD + 128 + tx * 4] =
            make_float4(acc[a][4], acc[a][5], acc[a][6], acc[a][7]);
    }
}

// ---------------------------------------------------------------------------
// Kernel 2: src[i] = Wh[i,:].a[:D], dst[i] = Wh[i,:].a[D:].  One warp per (r,i).
// ---------------------------------------------------------------------------
__global__ void __launch_bounds__(256) srcdst_kernel(
    const float* __restrict__ a1, const float* __restrict__ a2,
    const float* __restrict__ a3)
{
    int gw = (blockIdx.x * 256 + threadIdx.x) >> 5;  // global warp id
    int lane = threadIdx.x & 31;
    int r = gw >> 12;            // / 4096
    int i = gw & (NN - 1);
    const float* __restrict__ av = (r == 0) ? a1 : ((r == 1) ? a2 : a3);
    const float* __restrict__ wh = g_Wh[r] + (size_t)i * DD;

    float s = 0.f, d = 0.f;
#pragma unroll
    for (int t = 0; t < 8; t++) {
        float w = wh[lane + 32 * t];
        s += w * av[lane + 32 * t];
        d += w * av[DD + lane + 32 * t];
    }
#pragma unroll
    for (int off = 16; off; off >>= 1) {
        s += __shfl_xor_sync(0xffffffffu, s, off);
        d += __shfl_xor_sync(0xffffffffu, d, off);
    }
    if (lane == 0) { g_src[r][i] = s; g_dst[r][i] = d; }
}

// ---------------------------------------------------------------------------
// Kernel 3 (fused pass-B): out3[r][i,:] = (1/l_i) * sum_j p_ij * Wh[j,:]
//   p_ij = A_ij * exp(leaky(src_i + dst_j))   (no max subtraction needed:
//   |src+dst| <~ 7 so exp is safe in fp32, and softmax normalization makes the
//   result identical)
//   l_i accumulated in-block alongside the GEMM.
// BM=64 rows, BN=256 (full D), BK=32.  256 threads, 8x8 micro-tile/thread.
// ---------------------------------------------------------------------------
__global__ void __launch_bounds__(256, 2) passb_kernel(
    const int* __restrict__ A1, const int* __restrict__ A2,
    const int* __restrict__ A3)
{
    const int r = blockIdx.y;
    const int* __restrict__ A = (r == 0) ? A1 : ((r == 1) ? A2 : A3);
    const int i0 = blockIdx.x * BM;
    const float* __restrict__ Wh = g_Wh[r];
    const float* __restrict__ dst = g_dst[r];

    __shared__ float Ps[BM][33];     // [i][j], pad->conflict-free scalar stores
    __shared__ float Whs[32][DD];    // [j][d]
    __shared__ float s_src[BM];
    __shared__ float s_l[BM];

    const int tid = threadIdx.x;
    const int ty = tid >> 5;          // 0..7  -> rows ty*8 .. ty*8+7
    const int tx = tid & 31;          // cols tx*4..+3 and 128+tx*4..+3
    const int pi  = tid >> 2;         // P-build: row 0..63
    const int pjg = (tid & 3) << 3;   // P-build: j offset 0,8,16,24

    if (tid < BM) {
        s_src[tid] = g_src[r][i0 + tid];
        s_l[tid] = 0.f;
    }
    __syncthreads();

    const float src_i = s_src[pi];

    float acc[8][8];
#pragma unroll
    for (int a = 0; a < 8; a++)
#pragma unroll
        for (int b = 0; b < 8; b++) acc[a][b] = 0.f;

    for (int j0 = 0; j0 < NN; j0 += 32) {
        // ---- Wh tile [32][256]: 8 float4 per thread, fully coalesced ----
        {
            int row = tid >> 6;       // 0..3
            int q   = tid & 63;       // float4 index within 256-wide row
#pragma unroll
            for (int t = 0; t < 8; t++) {
                *(float4*)&Whs[row + t * 4][q * 4] =
                    *(const float4*)(Wh + (size_t)(j0 + row + t * 4) * DD + q * 4);
            }
        }
        // ---- P tile + row-sum partials.  A loads: 2x int4, coalesced ----
        {
            const int* ap = A + (size_t)(i0 + pi) * NN + j0 + pjg;
            int4 q0 = *(const int4*)ap;
            int4 q1 = *(const int4*)(ap + 4);
            float4 d0 = *(const float4*)(dst + j0 + pjg);
            float4 d1 = *(const float4*)(dst + j0 + pjg + 4);
            int   aa[8] = {q0.x, q0.y, q0.z, q0.w, q1.x, q1.y, q1.z, q1.w};
            float dv[8] = {d0.x, d0.y, d0.z, d0.w, d1.x, d1.y, d1.z, d1.w};
            float lp = 0.f;
#pragma unroll
            for (int q = 0; q < 8; q++) {
                float s = src_i + dv[q];
                float e = (s > 0.f) ? s : 0.2f * s;
                float p = aa[q] ? __expf(e) : 0.f;
                Ps[pi][pjg + q] = p;
                lp += p;
            }
            lp += __shfl_xor_sync(0xffffffffu, lp, 1);
            lp += __shfl_xor_sync(0xffffffffu, lp, 2);
            if ((tid & 3) == 0) s_l[pi] += lp;   // single writer per row
        }
        __syncthreads();

        // ---- GEMM: acc += P(64x32) * Whs(32x256) ----
#pragma unroll
        for (int kk = 0; kk < 32; kk++) {
            float bv[8];
            *(float4*)&bv[0] = *(const float4*)&Whs[kk][tx * 4];
            *(float4*)&bv[4] = *(const float4*)&Whs[kk][128 + tx * 4];
#pragma unroll
            for (int a = 0; a < 8; a++) {
                float av = Ps[ty * 8 + a][kk];   // warp broadcast
#pragma unroll
                for (int b = 0; b < 8; b++) acc[a][b] += av * bv[b];
            }
        }
        __syncthreads();
    }

    // ---- epilogue: normalize by row sums (s_l complete after last sync) ----
    float* out = g_out3[r];
#pragma unroll
    for (int a = 0; a < 8; a++) {
        int i = i0 + ty * 8 + a;
        float l = s_l[ty * 8 + a];
        float sc = (l > 0.f) ? (1.f / l) : 0.f;
        *(float4*)&out[(size_t)i * DD + tx * 4] =
            make_float4(acc[a][0] * sc, acc[a][1] * sc, acc[a][2] * sc, acc[a][3] * sc);
        *(float4*)&out[(size_t)i * DD + 128 + tx * 4] =
            make_float4(acc[a][4] * sc, acc[a][5] * sc, acc[a][6] * sc, acc[a][7] * sc);
    }
}

// ---------------------------------------------------------------------------
// Kernel 4: out = out3[0] + out3[1] + out3[2] + bias
// ---------------------------------------------------------------------------
__global__ void __launch_bounds__(256) combine_kernel(
    const float* __restrict__ bias, float* __restrict__ out)
{
    int idx4 = blockIdx.x * 256 + threadIdx.x;   // float4 index
    int base = idx4 * 4;
    int d = base & (DD - 1);
    float4 v0 = *(const float4*)&g_out3[0][base];
    float4 v1 = *(const float4*)&g_out3[1][base];
    float4 v2 = *(const float4*)&g_out3[2][base];
    float4 b  = *(const float4*)&bias[d];
    float4 o;
    o.x = v0.x + v1.x + v2.x + b.x;
    o.y = v0.y + v1.y + v2.y + b.y;
    o.z = v0.z + v1.z + v2.z + b.z;
    o.w = v0.w + v1.w + v2.w + b.w;
    *(float4*)&out[base] = o;
}

// ---------------------------------------------------------------------------
extern "C" void kernel_launch(void* const* d_in, const int* in_sizes, int n_in,
                              void* d_out, int out_size)
{
    const float* H    = (const float*)d_in[0];
    const float* W1   = (const float*)d_in[1];
    const float* W2   = (const float*)d_in[2];
    const float* W3   = (const float*)d_in[3];
    const float* a1   = (const float*)d_in[4];
    const float* a2   = (const float*)d_in[5];
    const float* a3   = (const float*)d_in[6];
    const float* bias = (const float*)d_in[7];
    const int*   A1   = (const int*)d_in[8];
    const int*   A2   = (const int*)d_in[9];
    const int*   A3   = (const int*)d_in[10];
    float* out = (float*)d_out;

    dim3 wh_grid(NN / 32, 3);
    wh_gemm_kernel<<<wh_grid, 256>>>(H, W1, W2, W3);

    srcdst_kernel<<<3 * NN / 8, 256>>>(a1, a2, a3);

    dim3 pb_grid(NN / BM, 3);
    passb_kernel<<<pb_grid, 256>>>(A1, A2, A3);

    combine_kernel<<<NN * DD / 4 / 256, 256>>>(bias, out);
}

// round 4
// speedup vs baseline: 1.9566x; 1.9566x over previous
#include <cuda_runtime.h>
#include <cuda_fp16.h>
#include <math.h>
#include <stdint.h>

#define NN 4096
#define DD 256
#define BI 64      // passb: i-rows per CTA
#define BK 32      // passb: j per chunk
#define ASTR 40    // smem row stride in halves (80B, conflict-free frag loads)

// ---------------- scratch (device globals; no allocations allowed) ----------
__device__ float  g_Wh[3][NN * DD];      // fp32 Wh [i][d]
__device__ __half g_WhT[3][DD * NN];     // fp16 Wh transposed [d][j]
__device__ float  g_src[3][NN];
__device__ float  g_dst[3][NN];
__device__ float  g_out3[3][DD * NN];    // TRANSPOSED partials [d][i]

// ---------------------------------------------------------------------------
// Kernel 1: Wh_r = H @ W_r^T  (fp32 CUDA cores; small)
// ---------------------------------------------------------------------------
__global__ void __launch_bounds__(256) wh_gemm_kernel(
    const float* __restrict__ H,
    const float* __restrict__ W1, const float* __restrict__ W2,
    const float* __restrict__ W3)
{
    const int r = blockIdx.y;
    const float* __restrict__ W = (r == 0) ? W1 : ((r == 1) ? W2 : W3);
    const int i0 = blockIdx.x * 32;

    __shared__ float Hs[32][32];
    __shared__ float Ws[32][256];

    const int tid = threadIdx.x;
    const int ty = tid >> 5;
    const int tx = tid & 31;

    float acc[4][8];
#pragma unroll
    for (int a = 0; a < 4; a++)
#pragma unroll
        for (int b = 0; b < 8; b++) acc[a][b] = 0.f;

    for (int k0 = 0; k0 < DD; k0 += 32) {
        {
            int row = tid >> 3, q = tid & 7;
            float4 v = *(const float4*)(H + (size_t)(i0 + row) * DD + k0 + q * 4);
            Hs[row][q * 4 + 0] = v.x; Hs[row][q * 4 + 1] = v.y;
            Hs[row][q * 4 + 2] = v.z; Hs[row][q * 4 + 3] = v.w;
        }
        {
            const float* wp = W + (size_t)tid * DD + k0;
#pragma unroll
            for (int q = 0; q < 8; q++) {
                float4 v = *(const float4*)(wp + q * 4);
                Ws[q * 4 + 0][tid] = v.x; Ws[q * 4 + 1][tid] = v.y;
                Ws[q * 4 + 2][tid] = v.z; Ws[q * 4 + 3][tid] = v.w;
            }
        }
        __syncthreads();
#pragma unroll
        for (int kk = 0; kk < 32; kk++) {
            float bv[8];
            *(float4*)&bv[0] = *(const float4*)&Ws[kk][tx * 4];
            *(float4*)&bv[4] = *(const float4*)&Ws[kk][128 + tx * 4];
#pragma unroll
            for (int a = 0; a < 4; a++) {
                float av = Hs[ty * 4 + a][kk];
#pragma unroll
                for (int b = 0; b < 8; b++) acc[a][b] += av * bv[b];
            }
        }
        __syncthreads();
    }

    float* out = g_Wh[r];
#pragma unroll
    for (int a = 0; a < 4; a++) {
        int i = i0 + ty * 4 + a;
        *(float4*)&out[(size_t)i * DD + tx * 4] =
            make_float4(acc[a][0], acc[a][1], acc[a][2], acc[a][3]);
        *(float4*)&out[(size_t)i * DD + 128 + tx * 4] =
            make_float4(acc[a][4], acc[a][5], acc[a][6], acc[a][7]);
    }
}

// ---------------------------------------------------------------------------
// Kernel 1b: transpose+convert  g_WhT[r][d][i] = (half)g_Wh[r][i][d]
// ---------------------------------------------------------------------------
__global__ void __launch_bounds__(256) transpose_kernel()
{
    const int r  = blockIdx.z;
    const int i0 = blockIdx.x * 32;
    const int d0 = blockIdx.y * 32;
    __shared__ float t[32][33];

    const int tid = threadIdx.x;
    const int row = tid >> 3;        // 0..31
    const int q   = tid & 7;         // 0..7

    float4 v = *(const float4*)(g_Wh[r] + (size_t)(i0 + row) * DD + d0 + q * 4);
    t[row][q * 4 + 0] = v.x; t[row][q * 4 + 1] = v.y;
    t[row][q * 4 + 2] = v.z; t[row][q * 4 + 3] = v.w;
    __syncthreads();

    uint32_t u0, u1;
    {
        __half h0 = __float2half_rn(t[q * 4 + 0][row]);
        __half h1 = __float2half_rn(t[q * 4 + 1][row]);
        __half h2 = __float2half_rn(t[q * 4 + 2][row]);
        __half h3 = __float2half_rn(t[q * 4 + 3][row]);
        u0 = (uint32_t)__half_as_ushort(h0) | ((uint32_t)__half_as_ushort(h1) << 16);
        u1 = (uint32_t)__half_as_ushort(h2) | ((uint32_t)__half_as_ushort(h3) << 16);
    }
    *(uint2*)&g_WhT[r][(size_t)(d0 + row) * NN + i0 + q * 4] = make_uint2(u0, u1);
}

// ---------------------------------------------------------------------------
// Kernel 2: src/dst projections
// ---------------------------------------------------------------------------
__global__ void __launch_bounds__(256) srcdst_kernel(
    const float* __restrict__ a1, const float* __restrict__ a2,
    const float* __restrict__ a3)
{
    int gw = (blockIdx.x * 256 + threadIdx.x) >> 5;
    int lane = threadIdx.x & 31;
    int r = gw >> 12;
    int i = gw & (NN - 1);
    const float* __restrict__ av = (r == 0) ? a1 : ((r == 1) ? a2 : a3);
    const float* __restrict__ wh = g_Wh[r] + (size_t)i * DD;

    float s = 0.f, d = 0.f;
#pragma unroll
    for (int t = 0; t < 8; t++) {
        float w = wh[lane + 32 * t];
        s += w * av[lane + 32 * t];
        d += w * av[DD + lane + 32 * t];
    }
#pragma unroll
    for (int off = 16; off; off >>= 1) {
        s += __shfl_xor_sync(0xffffffffu, s, off);
        d += __shfl_xor_sync(0xffffffffu, d, off);
    }
    if (lane == 0) { g_src[r][i] = s; g_dst[r][i] = d; }
}

// ---------------------------------------------------------------------------
// Kernel 3: pass-B on mma.sync (HMMA).
// Computes TRANSPOSED product per CTA:
//   C[d][i] = sum_j WhT[d][j] * P[i][j],   d = 0..255, i = i0..i0+63
// then out3T[r][d][i] = C[d][i] / l_i.
// A-operand (row.col "row") = WhT tile [m=d][k=j]  (k-contiguous)
// B-operand (row.col "col") = P   tile [n=i][k=j]  (k-contiguous)
// 512 threads = 16 warps; warp tile 32(d) x 32(i); K chunks of 32.
// Double-buffered smem, one __syncthreads per chunk.
// ---------------------------------------------------------------------------
#define SOFF_AS0  0
#define SOFF_PS0  20480
#define SOFF_AS1  25600
#define SOFF_PS1  46080
#define SOFF_SRC  51200          // float[64]
#define SOFF_L    51456          // float[64]  (then reused as inv)
#define SMEM_PB   51712

__global__ void __launch_bounds__(512, 1) passb_mma_kernel(
    const int* __restrict__ A1, const int* __restrict__ A2,
    const int* __restrict__ A3)
{
    extern __shared__ char smem[];
    const int r = blockIdx.y;
    const int* __restrict__ A = (r == 0) ? A1 : ((r == 1) ? A2 : A3);
    const int i0 = blockIdx.x * BI;
    const __half* __restrict__ WhT = g_WhT[r];
    const float*  __restrict__ dst = g_dst[r];

    const int tid  = threadIdx.x;
    const int w    = tid >> 5;
    const int lane = tid & 31;

    float* s_src = (float*)(smem + SOFF_SRC);
    float* s_l   = (float*)(smem + SOFF_L);

    if (tid < BI) { s_src[tid] = g_src[r][i0 + tid]; s_l[tid] = 0.f; }
    __syncthreads();

    // P-build mapping: thread -> row i = tid>>3, j offset (tid&7)*4
    const int pi = tid >> 3;
    const int pj = (tid & 7) * 4;
    const float src_i = s_src[pi];
    float l_acc = 0.f;

    // A(WhT)-build mapping: q = tid&3 (16B chunk), d = tid>>2 (+128)
    const int aq = tid & 3;
    const int ad = tid >> 2;

    // warp tile: d-base = (w>>1)*32, i-base = (w&1)*32
    const int dwb = (w >> 1) * 32;
    const int nwb = (w & 1) * 32;

    float c[2][4][4];
#pragma unroll
    for (int mi = 0; mi < 2; mi++)
#pragma unroll
        for (int ni = 0; ni < 4; ni++)
#pragma unroll
            for (int e = 0; e < 4; e++) c[mi][ni][e] = 0.f;

#define BUILD_CHUNK(j0, As, Ps)                                               \
    {                                                                          \
        int4   avv = *(const int4*)(A + (size_t)(i0 + pi) * NN + (j0) + pj);   \
        float4 dvv = *(const float4*)(dst + (j0) + pj);                        \
        uint4  w0 = *(const uint4*)(WhT + (size_t)ad * NN + (j0) + aq * 8);    \
        uint4  w1 = *(const uint4*)(WhT + (size_t)(ad + 128) * NN + (j0) + aq * 8); \
        int   aa[4] = {avv.x, avv.y, avv.z, avv.w};                            \
        float dd2[4] = {dvv.x, dvv.y, dvv.z, dvv.w};                           \
        __half hh[4];                                                          \
        _Pragma("unroll")                                                      \
        for (int e = 0; e < 4; e++) {                                          \
            float s  = src_i + dd2[e];                                         \
            float lr = (s > 0.f) ? s : 0.2f * s;                               \
            float p  = aa[e] ? __expf(lr) : 0.f;                               \
            hh[e] = __float2half_rn(p);                                        \
            l_acc += __half2float(hh[e]);                                      \
        }                                                                      \
        uint2 pu;                                                              \
        pu.x = (uint32_t)__half_as_ushort(hh[0]) | ((uint32_t)__half_as_ushort(hh[1]) << 16); \
        pu.y = (uint32_t)__half_as_ushort(hh[2]) | ((uint32_t)__half_as_ushort(hh[3]) << 16); \
        *(uint2*)((Ps) + ((size_t)pi * ASTR + pj) * 2) = pu;                   \
        *(uint4*)((As) + ((size_t)ad * ASTR + aq * 8) * 2) = w0;               \
        *(uint4*)((As) + ((size_t)(ad + 128) * ASTR + aq * 8) * 2) = w1;       \
    }

#define MMA_CHUNK(As, Ps)                                                     \
    {                                                                          \
        const char* asb = (As);                                                \
        const char* psb = (Ps);                                                \
        _Pragma("unroll")                                                      \
        for (int kt = 0; kt < 2; kt++) {                                       \
            int kcol = kt * 16 + (lane & 3) * 2;                               \
            uint32_t a0[2], a1[2], a2[2], a3[2];                               \
            _Pragma("unroll")                                                  \
            for (int mi = 0; mi < 2; mi++) {                                   \
                int row = dwb + mi * 16 + (lane >> 2);                         \
                a0[mi] = *(const uint32_t*)(asb + ((size_t)row * ASTR + kcol) * 2);        \
                a1[mi] = *(const uint32_t*)(asb + ((size_t)(row + 8) * ASTR + kcol) * 2);  \
                a2[mi] = *(const uint32_t*)(asb + ((size_t)row * ASTR + kcol + 8) * 2);    \
                a3[mi] = *(const uint32_t*)(asb + ((size_t)(row + 8) * ASTR + kcol + 8) * 2); \
            }                                                                  \
            _Pragma("unroll")                                                  \
            for (int ni = 0; ni < 4; ni++) {                                   \
                int nrow = nwb + ni * 8 + (lane >> 2);                         \
                uint32_t b0 = *(const uint32_t*)(psb + ((size_t)nrow * ASTR + kcol) * 2);     \
                uint32_t b1 = *(const uint32_t*)(psb + ((size_t)nrow * ASTR + kcol + 8) * 2); \
                _Pragma("unroll")                                              \
                for (int mi = 0; mi < 2; mi++) {                               \
                    asm volatile(                                              \
                        "mma.sync.aligned.m16n8k16.row.col.f32.f16.f16.f32 "   \
                        "{%0,%1,%2,%3}, {%4,%5,%6,%7}, {%8,%9}, {%0,%1,%2,%3};"\
                        : "+f"(c[mi][ni][0]), "+f"(c[mi][ni][1]),              \
                          "+f"(c[mi][ni][2]), "+f"(c[mi][ni][3])               \
                        : "r"(a0[mi]), "r"(a1[mi]), "r"(a2[mi]), "r"(a3[mi]),  \
                          "r"(b0), "r"(b1));                                   \
                }                                                              \
            }                                                                  \
        }                                                                      \
    }

    // prologue: build chunk 0
    BUILD_CHUNK(0, (smem + SOFF_AS0), (smem + SOFF_PS0));
    __syncthreads();

    for (int cch = 0; cch < NN / BK; cch++) {
        if (cch & 1) {
            MMA_CHUNK((smem + SOFF_AS1), (smem + SOFF_PS1));
            if (cch + 1 < NN / BK)
                BUILD_CHUNK((cch + 1) * BK, (smem + SOFF_AS0), (smem + SOFF_PS0));
        } else {
            MMA_CHUNK((smem + SOFF_AS0), (smem + SOFF_PS0));
            if (cch + 1 < NN / BK)
                BUILD_CHUNK((cch + 1) * BK, (smem + SOFF_AS1), (smem + SOFF_PS1));
        }
        __syncthreads();
    }

    // ---- row sums -> 1/l (8 threads per i-row, contiguous in tid) ----
    l_acc += __shfl_xor_sync(0xffffffffu, l_acc, 1);
    l_acc += __shfl_xor_sync(0xffffffffu, l_acc, 2);
    l_acc += __shfl_xor_sync(0xffffffffu, l_acc, 4);
    if ((tid & 7) == 0) s_l[pi] = l_acc;
    __syncthreads();
    if (tid < BI) {
        float l = s_l[tid];
        s_l[tid] = (l > 0.f) ? (1.f / l) : 0.f;   // reuse as inv
    }
    __syncthreads();

    // ---- epilogue: scaled stores to transposed partial out3T[d][i] ----
    float* T = g_out3[r];
#pragma unroll
    for (int ni = 0; ni < 4; ni++) {
        int icol = nwb + ni * 8 + (lane & 3) * 2;  // local i
        float iv0 = s_l[icol];
        float iv1 = s_l[icol + 1];
#pragma unroll
        for (int mi = 0; mi < 2; mi++) {
            int d = dwb + mi * 16 + (lane >> 2);
            *(float2*)&T[(size_t)d * NN + i0 + icol] =
                make_float2(c[mi][ni][0] * iv0, c[mi][ni][1] * iv1);
            *(float2*)&T[(size_t)(d + 8) * NN + i0 + icol] =
                make_float2(c[mi][ni][2] * iv0, c[mi][ni][3] * iv1);
        }
    }
}

// ---------------------------------------------------------------------------
// Kernel 4: out[i][d] = sum_r out3T[r][d][i] + bias[d]   (tiled transpose)
// ---------------------------------------------------------------------------
__global__ void __launch_bounds__(256) combine_t_kernel(
    const float* __restrict__ bias, float* __restrict__ out)
{
    const int i0 = blockIdx.x * 32;
    const int d0 = blockIdx.y * 32;
    __shared__ float t[32][33];

    const int tid = threadIdx.x;
    const int ty = tid >> 5;      // 0..7
    const int tx = tid & 31;      // i-local

#pragma unroll
    for (int s = 0; s < 4; s++) {
        int dl = ty + s * 8;
        size_t off = (size_t)(d0 + dl) * NN + i0 + tx;
        t[dl][tx] = g_out3[0][off] + g_out3[1][off] + g_out3[2][off];
    }
    __syncthreads();

    const int il = tid >> 3;          // 0..31
    const int dq = (tid & 7) * 4;     // 0..28
    float4 b = *(const float4*)&bias[d0 + dq];
    float4 v;
    v.x = t[dq + 0][il] + b.x;
    v.y = t[dq + 1][il] + b.y;
    v.z = t[dq + 2][il] + b.z;
    v.w = t[dq + 3][il] + b.w;
    *(float4*)&out[(size_t)(i0 + il) * DD + d0 + dq] = v;
}

// ---------------------------------------------------------------------------
extern "C" void kernel_launch(void* const* d_in, const int* in_sizes, int n_in,
                              void* d_out, int out_size)
{
    const float* H    = (const float*)d_in[0];
    const float* W1   = (const float*)d_in[1];
    const float* W2   = (const float*)d_in[2];
    const float* W3   = (const float*)d_in[3];
    const float* a1   = (const float*)d_in[4];
    const float* a2   = (const float*)d_in[5];
    const float* a3   = (const float*)d_in[6];
    const float* bias = (const float*)d_in[7];
    const int*   A1   = (const int*)d_in[8];
    const int*   A2   = (const int*)d_in[9];
    const int*   A3   = (const int*)d_in[10];
    float* out = (float*)d_out;

    dim3 wh_grid(NN / 32, 3);
    wh_gemm_kernel<<<wh_grid, 256>>>(H, W1, W2, W3);

    dim3 tr_grid(NN / 32, DD / 32, 3);
    transpose_kernel<<<tr_grid, 256>>>();

    srcdst_kernel<<<3 * NN / 8, 256>>>(a1, a2, a3);

    cudaFuncSetAttribute(passb_mma_kernel,
                         cudaFuncAttributeMaxDynamicSharedMemorySize, SMEM_PB);
    dim3 pb_grid(NN / BI, 3);
    passb_mma_kernel<<<pb_grid, 512, SMEM_PB>>>(A1, A2, A3);

    dim3 cb_grid(NN / 32, DD / 32);
    combine_t_kernel<<<cb_grid, 256>>>(bias, out);
}

// round 5
// speedup vs baseline: 2.1701x; 1.1091x over previous
#include <cuda_runtime.h>
#include <cuda_fp16.h>
#include <math.h>
#include <stdint.h>

#define NN 4096
#define DD 256
#define BI 64      // passb: i-rows per CTA
#define BK 32      // passb: j per chunk
#define ASTR 40    // smem row stride in halves (80B, conflict-free frag loads)

// ---------------- scratch (device globals; no allocations allowed) ----------
__device__ float  g_Wh[3][NN * DD];      // fp32 Wh [i][d]
__device__ __half g_WhT[3][DD * NN];     // fp16 Wh transposed [d][j]
__device__ float4 g_ip[3][NN];           // {src, exp(src), exp(.2src), 0}
__device__ float4 g_jp[3][NN];           // {dst, exp(dst), exp(.2dst), 0}
__device__ float  g_out3[3][DD * NN];    // TRANSPOSED partials [d][i]

// ============================ helpers =======================================
__device__ __forceinline__ uint32_t smem_u32(const void* p) {
    uint32_t a;
    asm("{ .reg .u64 t; cvta.to.shared.u64 t, %1; cvt.u32.u64 %0, t; }"
        : "=r"(a) : "l"(p));
    return a;
}
__device__ __forceinline__ void cp16(uint32_t dst, const void* src) {
    asm volatile("cp.async.cg.shared.global [%0], [%1], 16;"
                 :: "r"(dst), "l"(src) : "memory");
}
#define CP_COMMIT() asm volatile("cp.async.commit_group;" ::: "memory")
#define CP_WAIT0()  asm volatile("cp.async.wait_group 0;" ::: "memory")

// ---------------------------------------------------------------------------
// Kernel 1: Wh_r = H @ W_r^T  (fp32 CUDA cores; ~0.8 G FMA)
// ---------------------------------------------------------------------------
__global__ void __launch_bounds__(256) wh_gemm_kernel(
    const float* __restrict__ H,
    const float* __restrict__ W1, const float* __restrict__ W2,
    const float* __restrict__ W3)
{
    const int r = blockIdx.y;
    const float* __restrict__ W = (r == 0) ? W1 : ((r == 1) ? W2 : W3);
    const int i0 = blockIdx.x * 32;

    __shared__ float Hs[32][32];
    __shared__ float Ws[32][256];

    const int tid = threadIdx.x;
    const int ty = tid >> 5;
    const int tx = tid & 31;

    float acc[4][8];
#pragma unroll
    for (int a = 0; a < 4; a++)
#pragma unroll
        for (int b = 0; b < 8; b++) acc[a][b] = 0.f;

    for (int k0 = 0; k0 < DD; k0 += 32) {
        {
            int row = tid >> 3, q = tid & 7;
            float4 v = *(const float4*)(H + (size_t)(i0 + row) * DD + k0 + q * 4);
            Hs[row][q * 4 + 0] = v.x; Hs[row][q * 4 + 1] = v.y;
            Hs[row][q * 4 + 2] = v.z; Hs[row][q * 4 + 3] = v.w;
        }
        {
            const float* wp = W + (size_t)tid * DD + k0;
#pragma unroll
            for (int q = 0; q < 8; q++) {
                float4 v = *(const float4*)(wp + q * 4);
                Ws[q * 4 + 0][tid] = v.x; Ws[q * 4 + 1][tid] = v.y;
                Ws[q * 4 + 2][tid] = v.z; Ws[q * 4 + 3][tid] = v.w;
            }
        }
        __syncthreads();
#pragma unroll
        for (int kk = 0; kk < 32; kk++) {
            float bv[8];
            *(float4*)&bv[0] = *(const float4*)&Ws[kk][tx * 4];
            *(float4*)&bv[4] = *(const float4*)&Ws[kk][128 + tx * 4];
#pragma unroll
            for (int a = 0; a < 4; a++) {
                float av = Hs[ty * 4 + a][kk];
#pragma unroll
                for (int b = 0; b < 8; b++) acc[a][b] += av * bv[b];
            }
        }
        __syncthreads();
    }

    float* out = g_Wh[r];
#pragma unroll
    for (int a = 0; a < 4; a++) {
        int i = i0 + ty * 4 + a;
        *(float4*)&out[(size_t)i * DD + tx * 4] =
            make_float4(acc[a][0], acc[a][1], acc[a][2], acc[a][3]);
        *(float4*)&out[(size_t)i * DD + 128 + tx * 4] =
            make_float4(acc[a][4], acc[a][5], acc[a][6], acc[a][7]);
    }
}

// ---------------------------------------------------------------------------
// Kernel 1b: transpose+convert  g_WhT[r][d][i] = (half)g_Wh[r][i][d]
// ---------------------------------------------------------------------------
__global__ void __launch_bounds__(256) transpose_kernel()
{
    const int r  = blockIdx.z;
    const int i0 = blockIdx.x * 32;
    const int d0 = blockIdx.y * 32;
    __shared__ float t[32][33];

    const int tid = threadIdx.x;
    const int row = tid >> 3;
    const int q   = tid & 7;

    float4 v = *(const float4*)(g_Wh[r] + (size_t)(i0 + row) * DD + d0 + q * 4);
    t[row][q * 4 + 0] = v.x; t[row][q * 4 + 1] = v.y;
    t[row][q * 4 + 2] = v.z; t[row][q * 4 + 3] = v.w;
    __syncthreads();

    uint32_t u0, u1;
    {
        __half h0 = __float2half_rn(t[q * 4 + 0][row]);
        __half h1 = __float2half_rn(t[q * 4 + 1][row]);
        __half h2 = __float2half_rn(t[q * 4 + 2][row]);
        __half h3 = __float2half_rn(t[q * 4 + 3][row]);
        u0 = (uint32_t)__half_as_ushort(h0) | ((uint32_t)__half_as_ushort(h1) << 16);
        u1 = (uint32_t)__half_as_ushort(h2) | ((uint32_t)__half_as_ushort(h3) << 16);
    }
    *(uint2*)&g_WhT[r][(size_t)(d0 + row) * NN + i0 + q * 4] = make_uint2(u0, u1);
}

// ---------------------------------------------------------------------------
// Kernel 2: src/dst projections + factorized-exp packs
// ---------------------------------------------------------------------------
__global__ void __launch_bounds__(256) srcdst_kernel(
    const float* __restrict__ a1, const float* __restrict__ a2,
    const float* __restrict__ a3)
{
    int gw = (blockIdx.x * 256 + threadIdx.x) >> 5;
    int lane = threadIdx.x & 31;
    int r = gw >> 12;
    int i = gw & (NN - 1);
    const float* __restrict__ av = (r == 0) ? a1 : ((r == 1) ? a2 : a3);
    const float* __restrict__ wh = g_Wh[r] + (size_t)i * DD;

    float s = 0.f, d = 0.f;
#pragma unroll
    for (int t = 0; t < 8; t++) {
        float w = wh[lane + 32 * t];
        s += w * av[lane + 32 * t];
        d += w * av[DD + lane + 32 * t];
    }
#pragma unroll
    for (int off = 16; off; off >>= 1) {
        s += __shfl_xor_sync(0xffffffffu, s, off);
        d += __shfl_xor_sync(0xffffffffu, d, off);
    }
    if (lane == 0) {
        g_ip[r][i] = make_float4(s, expf(s), expf(0.2f * s), 0.f);
        g_jp[r][i] = make_float4(d, expf(d), expf(0.2f * d), 0.f);
    }
}

// ---------------------------------------------------------------------------
// Kernel 3: pass-B on mma.sync (HMMA), cp.async pipelined, no per-edge exp.
//   C[d][i] = sum_j WhT[d][j] * P[i][j];  out3T[r][d][i] = C[d][i]/l_i
//   P[i][j] = A_ij * (s>0 ? E1_i*F1_j : E2_i*F2_j),  s = src_i + dst_j
// 512 threads = 16 warps; warp tile 32(d) x 32(i); K chunks of 32.
// ---------------------------------------------------------------------------
#define SO_WH0  0          // 256*40 halves = 20480 B
#define SO_WH1  20480
#define SO_A0   40960      // 64*32 ints = 8192 B
#define SO_A1   49152
#define SO_JP0  57344      // 32 float4 = 512 B
#define SO_JP1  57856
#define SO_P0   58368      // 64*40 halves = 5120 B
#define SO_P1   63488
#define SO_L    68608      // float[64]
#define SMEM_PB 68864

__global__ void __launch_bounds__(512, 1) passb_mma_kernel(
    const int* __restrict__ A1, const int* __restrict__ A2,
    const int* __restrict__ A3)
{
    extern __shared__ char smem[];
    const uint32_t sb = smem_u32(smem);
    const int r = blockIdx.y;
    const int* __restrict__ A = (r == 0) ? A1 : ((r == 1) ? A2 : A3);
    const int i0 = blockIdx.x * BI;
    const __half*  __restrict__ WhT = g_WhT[r];
    const float4*  __restrict__ jp  = g_jp[r];

    const int tid  = threadIdx.x;
    const int w    = tid >> 5;
    const int lane = tid & 31;

    float* s_l = (float*)(smem + SO_L);
    if (tid < BI) s_l[tid] = 0.f;

    // per-thread i-row data for the P build
    const int pi  = tid >> 3;          // 0..63
    const int pjq = tid & 7;           // 0..7 -> j offset pjq*4
    float4 ip = g_ip[r][i0 + pi];
    const float src_i = ip.x, E1 = ip.y, E2 = ip.z;
    float l_acc = 0.f;

    // Wh cp.async mapping: items tid and tid+512: d = idx>>2, piece = idx&3
    const int whd0 = tid >> 2, whp0 = tid & 3;
    const int whd1 = (tid + 512) >> 2, whp1 = (tid + 512) & 3;

    const int dwb = (w >> 1) * 32;
    const int nwb = (w & 1) * 32;

    float c[2][4][4];
#pragma unroll
    for (int mi = 0; mi < 2; mi++)
#pragma unroll
        for (int ni = 0; ni < 4; ni++)
#pragma unroll
            for (int e = 0; e < 4; e++) c[mi][ni][e] = 0.f;

#define ISSUE_CHUNK(j0, WHOFF, AOFF, JPOFF)                                    \
    {                                                                          \
        cp16(sb + (WHOFF) + whd0 * 80 + whp0 * 16,                             \
             WhT + (size_t)whd0 * NN + (j0) + whp0 * 8);                       \
        cp16(sb + (WHOFF) + whd1 * 80 + whp1 * 16,                             \
             WhT + (size_t)whd1 * NN + (j0) + whp1 * 8);                       \
        cp16(sb + (AOFF) + tid * 16,                                           \
             A + (size_t)(i0 + pi) * NN + (j0) + pjq * 4);                     \
        if (tid < 32) cp16(sb + (JPOFF) + tid * 16, jp + (j0) + tid);          \
        CP_COMMIT();                                                           \
    }

#define BUILD_P(AOFF, JPOFF, POFF)                                             \
    {                                                                          \
        int4 avv;                                                              \
        asm volatile("ld.shared.v4.u32 {%0,%1,%2,%3}, [%4];"                   \
            : "=r"(avv.x), "=r"(avv.y), "=r"(avv.z), "=r"(avv.w)               \
            : "r"(sb + (AOFF) + tid * 16));                                    \
        int aa[4] = {avv.x, avv.y, avv.z, avv.w};                              \
        __half hh[4];                                                          \
        _Pragma("unroll")                                                      \
        for (int e = 0; e < 4; e++) {                                          \
            float4 jv = *(const float4*)(smem + (JPOFF) + pjq * 64 + e * 16);  \
            float s = src_i + jv.x;                                            \
            float p = (s > 0.f) ? (E1 * jv.y) : (E2 * jv.z);                   \
            p = aa[e] ? p : 0.f;                                               \
            hh[e] = __float2half_rn(p);                                        \
            l_acc += __half2float(hh[e]);                                      \
        }                                                                      \
        uint2 pu;                                                              \
        pu.x = (uint32_t)__half_as_ushort(hh[0]) |                             \
               ((uint32_t)__half_as_ushort(hh[1]) << 16);                      \
        pu.y = (uint32_t)__half_as_ushort(hh[2]) |                             \
               ((uint32_t)__half_as_ushort(hh[3]) << 16);                      \
        *(uint2*)(smem + (POFF) + pi * 80 + pjq * 8) = pu;                     \
    }

#define MMA_CHUNK(As, Ps)                                                      \
    {                                                                          \
        const char* asb = (As);                                                \
        const char* psb = (Ps);                                                \
        _Pragma("unroll")                                                      \
        for (int kt = 0; kt < 2; kt++) {                                       \
            int kcol = kt * 16 + (lane & 3) * 2;                               \
            uint32_t a0[2], a1[2], a2[2], a3[2];                               \
            _Pragma("unroll")                                                  \
            for (int mi = 0; mi < 2; mi++) {                                   \
                int row = dwb + mi * 16 + (lane >> 2);                         \
                a0[mi] = *(const uint32_t*)(asb + ((size_t)row * ASTR + kcol) * 2);        \
                a1[mi] = *(const uint32_t*)(asb + ((size_t)(row + 8) * ASTR + kcol) * 2);  \
                a2[mi] = *(const uint32_t*)(asb + ((size_t)row * ASTR + kcol + 8) * 2);    \
                a3[mi] = *(const uint32_t*)(asb + ((size_t)(row + 8) * ASTR + kcol + 8) * 2); \
            }                                                                  \
            _Pragma("unroll")                                                  \
            for (int ni = 0; ni < 4; ni++) {                                   \
                int nrow = nwb + ni * 8 + (lane >> 2);                         \
                uint32_t b0 = *(const uint32_t*)(psb + ((size_t)nrow * ASTR + kcol) * 2);     \
                uint32_t b1 = *(const uint32_t*)(psb + ((size_t)nrow * ASTR + kcol + 8) * 2); \
                _Pragma("unroll")                                              \
                for (int mi = 0; mi < 2; mi++) {                               \
                    asm volatile(                                              \
                        "mma.sync.aligned.m16n8k16.row.col.f32.f16.f16.f32 "   \
                        "{%0,%1,%2,%3}, {%4,%5,%6,%7}, {%8,%9}, {%0,%1,%2,%3};"\
                        : "+f"(c[mi][ni][0]), "+f"(c[mi][ni][1]),              \
                          "+f"(c[mi][ni][2]), "+f"(c[mi][ni][3])               \
                        : "r"(a0[mi]), "r"(a1[mi]), "r"(a2[mi]), "r"(a3[mi]),  \
                          "r"(b0), "r"(b1));                                   \
                }                                                              \
            }                                                                  \
        }                                                                      \
    }

    // prologue: start loads for chunk 0
    ISSUE_CHUNK(0, SO_WH0, SO_A0, SO_JP0);

    for (int cch = 0; cch < NN / BK; cch++) {
        const int j1 = (cch + 1) * BK;
        CP_WAIT0();
        __syncthreads();   // chunk-c data visible; prev MMA reads done
        if (cch & 1) {
            if (cch + 1 < NN / BK) ISSUE_CHUNK(j1, SO_WH0, SO_A0, SO_JP0);
            BUILD_P(SO_A1, SO_JP1, SO_P1);
            __syncthreads();
            MMA_CHUNK((smem + SO_WH1), (smem + SO_P1));
        } else {
            if (cch + 1 < NN / BK) ISSUE_CHUNK(j1, SO_WH1, SO_A1, SO_JP1);
            BUILD_P(SO_A0, SO_JP0, SO_P0);
            __syncthreads();
            MMA_CHUNK((smem + SO_WH0), (smem + SO_P0));
        }
    }

    // ---- row sums -> 1/l ----
    l_acc += __shfl_xor_sync(0xffffffffu, l_acc, 1);
    l_acc += __shfl_xor_sync(0xffffffffu, l_acc, 2);
    l_acc += __shfl_xor_sync(0xffffffffu, l_acc, 4);
    __syncthreads();
    if ((tid & 7) == 0) s_l[pi] = l_acc;
    __syncthreads();
    if (tid < BI) {
        float l = s_l[tid];
        s_l[tid] = (l > 0.f) ? (1.f / l) : 0.f;
    }
    __syncthreads();

    // ---- epilogue: scaled stores to transposed partials out3T[d][i] ----
    float* T = g_out3[r];
#pragma unroll
    for (int ni = 0; ni < 4; ni++) {
        int icol = nwb + ni * 8 + (lane & 3) * 2;
        float iv0 = s_l[icol];
        float iv1 = s_l[icol + 1];
#pragma unroll
        for (int mi = 0; mi < 2; mi++) {
            int d = dwb + mi * 16 + (lane >> 2);
            *(float2*)&T[(size_t)d * NN + i0 + icol] =
                make_float2(c[mi][ni][0] * iv0, c[mi][ni][1] * iv1);
            *(float2*)&T[(size_t)(d + 8) * NN + i0 + icol] =
                make_float2(c[mi][ni][2] * iv0, c[mi][ni][3] * iv1);
        }
    }
}

// ---------------------------------------------------------------------------
// Kernel 4: out[i][d] = sum_r out3T[r][d][i] + bias[d]
// ---------------------------------------------------------------------------
__global__ void __launch_bounds__(256) combine_t_kernel(
    const float* __restrict__ bias, float* __restrict__ out)
{
    const int i0 = blockIdx.x * 32;
    const int d0 = blockIdx.y * 32;
    __shared__ float t[32][33];

    const int tid = threadIdx.x;
    const int ty = tid >> 5;
    const int tx = tid & 31;

#pragma unroll
    for (int s = 0; s < 4; s++) {
        int dl = ty + s * 8;
        size_t off = (size_t)(d0 + dl) * NN + i0 + tx;
        t[dl][tx] = g_out3[0][off] + g_out3[1][off] + g_out3[2][off];
    }
    __syncthreads();

    const int il = tid >> 3;
    const int dq = (tid & 7) * 4;
    float4 b = *(const float4*)&bias[d0 + dq];
    float4 v;
    v.x = t[dq + 0][il] + b.x;
    v.y = t[dq + 1][il] + b.y;
    v.z = t[dq + 2][il] + b.z;
    v.w = t[dq + 3][il] + b.w;
    *(float4*)&out[(size_t)(i0 + il) * DD + d0 + dq] = v;
}

// ---------------------------------------------------------------------------
extern "C" void kernel_launch(void* const* d_in, const int* in_sizes, int n_in,
                              void* d_out, int out_size)
{
    const float* H    = (const float*)d_in[0];
    const float* W1   = (const float*)d_in[1];
    const float* W2   = (const float*)d_in[2];
    const float* W3   = (const float*)d_in[3];
    const float* a1   = (const float*)d_in[4];
    const float* a2   = (const float*)d_in[5];
    const float* a3   = (const float*)d_in[6];
    const float* bias = (const float*)d_in[7];
    const int*   A1   = (const int*)d_in[8];
    const int*   A2   = (const int*)d_in[9];
    const int*   A3   = (const int*)d_in[10];
    float* out = (float*)d_out;

    dim3 wh_grid(NN / 32, 3);
    wh_gemm_kernel<<<wh_grid, 256>>>(H, W1, W2, W3);

    dim3 tr_grid(NN / 32, DD / 32, 3);
    transpose_kernel<<<tr_grid, 256>>>();

    srcdst_kernel<<<3 * NN / 8, 256>>>(a1, a2, a3);

    cudaFuncSetAttribute(passb_mma_kernel,
                         cudaFuncAttributeMaxDynamicSharedMemorySize, SMEM_PB);
    dim3 pb_grid(NN / BI, 3);
    passb_mma_kernel<<<pb_grid, 512, SMEM_PB>>>(A1, A2, A3);

    dim3 cb_grid(NN / 32, DD / 32);
    combine_t_kernel<<<cb_grid, 256>>>(bias, out);
}

// round 7
// speedup vs baseline: 2.3308x; 1.0741x over previous
#include <cuda_runtime.h>
#include <cuda_fp16.h>
#include <math.h>
#include <stdint.h>

#define NN 4096
#define DD 256
#define BI 64      // passb: i-rows per CTA
#define BK 32      // passb: j per chunk
#define ASTR 40    // smem row stride in halves (80B, conflict-free frags)
#define NCH (NN / BK)

// ---------------- scratch (device globals; no allocations allowed) ----------
__device__ float  g_Wh[3][NN * DD];      // fp32 Wh [i][d]
__device__ __half g_WhT[3][DD * NN];     // fp16 Wh transposed [d][j]
__device__ float4 g_ip[3][NN];           // {src, exp(src), exp(.2src), 0}
__device__ float4 g_jp[3][NN];           // {dst, exp(dst), exp(.2dst), 0}
__device__ float  g_out3[3][DD * NN];    // TRANSPOSED partials [d][i]

// ============================ helpers =======================================
__device__ __forceinline__ uint32_t smem_u32(const void* p) {
    uint32_t a;
    asm("{ .reg .u64 t; cvta.to.shared.u64 t, %1; cvt.u32.u64 %0, t; }"
        : "=r"(a) : "l"(p));
    return a;
}
__device__ __forceinline__ void cp16(uint32_t dst, const void* src) {
    asm volatile("cp.async.cg.shared.global [%0], [%1], 16;"
                 :: "r"(dst), "l"(src) : "memory");
}
#define CP_COMMIT() asm volatile("cp.async.commit_group;" ::: "memory")
#define CP_WAIT2()  asm volatile("cp.async.wait_group 2;" ::: "memory")

#define LDM4(r0, r1, r2, r3, addr)                                             \
    asm volatile("ldmatrix.sync.aligned.m8n8.x4.shared.b16 {%0,%1,%2,%3}, [%4];" \
                 : "=r"(r0), "=r"(r1), "=r"(r2), "=r"(r3) : "r"(addr))

// ---------------------------------------------------------------------------
// Kernel 1: Wh_r = H @ W_r^T  (fp32 CUDA cores; ~0.8 G FMA)
// ---------------------------------------------------------------------------
__global__ void __launch_bounds__(256) wh_gemm_kernel(
    const float* __restrict__ H,
    const float* __restrict__ W1, const float* __restrict__ W2,
    const float* __restrict__ W3)
{
    const int r = blockIdx.y;
    const float* __restrict__ W = (r == 0) ? W1 : ((r == 1) ? W2 : W3);
    const int i0 = blockIdx.x * 32;

    __shared__ float Hs[32][32];
    __shared__ float Ws[32][256];

    const int tid = threadIdx.x;
    const int ty = tid >> 5;
    const int tx = tid & 31;

    float acc[4][8];
#pragma unroll
    for (int a = 0; a < 4; a++)
#pragma unroll
        for (int b = 0; b < 8; b++) acc[a][b] = 0.f;

    for (int k0 = 0; k0 < DD; k0 += 32) {
        {
            int row = tid >> 3, q = tid & 7;
            float4 v = *(const float4*)(H + (size_t)(i0 + row) * DD + k0 + q * 4);
            Hs[row][q * 4 + 0] = v.x; Hs[row][q * 4 + 1] = v.y;
            Hs[row][q * 4 + 2] = v.z; Hs[row][q * 4 + 3] = v.w;
        }
        {
            const float* wp = W + (size_t)tid * DD + k0;
#pragma unroll
            for (int q = 0; q < 8; q++) {
                float4 v = *(const float4*)(wp + q * 4);
                Ws[q * 4 + 0][tid] = v.x; Ws[q * 4 + 1][tid] = v.y;
                Ws[q * 4 + 2][tid] = v.z; Ws[q * 4 + 3][tid] = v.w;
            }
        }
        __syncthreads();
#pragma unroll
        for (int kk = 0; kk < 32; kk++) {
            float bv[8];
            *(float4*)&bv[0] = *(const float4*)&Ws[kk][tx * 4];
            *(float4*)&bv[4] = *(const float4*)&Ws[kk][128 + tx * 4];
#pragma unroll
            for (int a = 0; a < 4; a++) {
                float av = Hs[ty * 4 + a][kk];
#pragma unroll
                for (int b = 0; b < 8; b++) acc[a][b] += av * bv[b];
            }
        }
        __syncthreads();
    }

    float* out = g_Wh[r];
#pragma unroll
    for (int a = 0; a < 4; a++) {
        int i = i0 + ty * 4 + a;
        *(float4*)&out[(size_t)i * DD + tx * 4] =
            make_float4(acc[a][0], acc[a][1], acc[a][2], acc[a][3]);
        *(float4*)&out[(size_t)i * DD + 128 + tx * 4] =
            make_float4(acc[a][4], acc[a][5], acc[a][6], acc[a][7]);
    }
}

// ---------------------------------------------------------------------------
// Kernel 1b: transpose+convert  g_WhT[r][d][i] = (half)g_Wh[r][i][d]
// ---------------------------------------------------------------------------
__global__ void __launch_bounds__(256) transpose_kernel()
{
    const int r  = blockIdx.z;
    const int i0 = blockIdx.x * 32;
    const int d0 = blockIdx.y * 32;
    __shared__ float t[32][33];

    const int tid = threadIdx.x;
    const int row = tid >> 3;
    const int q   = tid & 7;

    float4 v = *(const float4*)(g_Wh[r] + (size_t)(i0 + row) * DD + d0 + q * 4);
    t[row][q * 4 + 0] = v.x; t[row][q * 4 + 1] = v.y;
    t[row][q * 4 + 2] = v.z; t[row][q * 4 + 3] = v.w;
    __syncthreads();

    uint32_t u0, u1;
    {
        __half h0 = __float2half_rn(t[q * 4 + 0][row]);
        __half h1 = __float2half_rn(t[q * 4 + 1][row]);
        __half h2 = __float2half_rn(t[q * 4 + 2][row]);
        __half h3 = __float2half_rn(t[q * 4 + 3][row]);
        u0 = (uint32_t)__half_as_ushort(h0) | ((uint32_t)__half_as_ushort(h1) << 16);
        u1 = (uint32_t)__half_as_ushort(h2) | ((uint32_t)__half_as_ushort(h3) << 16);
    }
    *(uint2*)&g_WhT[r][(size_t)(d0 + row) * NN + i0 + q * 4] = make_uint2(u0, u1);
}

// ---------------------------------------------------------------------------
// Kernel 2: src/dst projections + factorized-exp packs
// ---------------------------------------------------------------------------
__global__ void __launch_bounds__(256) srcdst_kernel(
    const float* __restrict__ a1, const float* __restrict__ a2,
    const float* __restrict__ a3)
{
    int gw = (blockIdx.x * 256 + threadIdx.x) >> 5;
    int lane = threadIdx.x & 31;
    int r = gw >> 12;
    int i = gw & (NN - 1);
    const float* __restrict__ av = (r == 0) ? a1 : ((r == 1) ? a2 : a3);
    const float* __restrict__ wh = g_Wh[r] + (size_t)i * DD;

    float s = 0.f, d = 0.f;
#pragma unroll
    for (int t = 0; t < 8; t++) {
        float w = wh[lane + 32 * t];
        s += w * av[lane + 32 * t];
        d += w * av[DD + lane + 32 * t];
    }
#pragma unroll
    for (int off = 16; off; off >>= 1) {
        s += __shfl_xor_sync(0xffffffffu, s, off);
        d += __shfl_xor_sync(0xffffffffu, d, off);
    }
    if (lane == 0) {
        g_ip[r][i] = make_float4(s, expf(s), expf(0.2f * s), 0.f);
        g_jp[r][i] = make_float4(d, expf(d), expf(0.2f * d), 0.f);
    }
}

// ---------------------------------------------------------------------------
// Kernel 3: pass-B on mma.sync, 4-stage cp.async pipeline, ldmatrix frags,
// register-prefetched A, no per-edge exp.
//   C[d][i] = sum_j WhT[d][j] * P[i][j];  out3T[r][d][i] = C[d][i]/l_i
//   P[i][j] = A_ij * (s>0 ? E1_i*F1_j : E2_i*F2_j),  s = src_i + dst_j
// 512 threads = 16 warps; warp tile 32(d) x 32(i); K chunks of 32; 4 stages.
// ---------------------------------------------------------------------------
#define SO_WH(s)  ((s) * 20480)            // 4 x 20480 = 81920
#define SO_JP(s)  (81920 + (s) * 512)      // 4 x 512
#define SO_P(b)   (83968 + (b) * 5120)     // 2 x 5120
#define SO_L      94208                    // float[64]
#define SMEM_PB   94464

__global__ void __launch_bounds__(512) passb_mma_kernel(
    const int* __restrict__ A1, const int* __restrict__ A2,
    const int* __restrict__ A3)
{
    extern __shared__ char smem[];
    const uint32_t sb = smem_u32(smem);
    const int r = blockIdx.y;
    const int* __restrict__ A = (r == 0) ? A1 : ((r == 1) ? A2 : A3);
    const int i0 = blockIdx.x * BI;
    const __half*  __restrict__ WhT = g_WhT[r];
    const float4*  __restrict__ jp  = g_jp[r];

    const int tid  = threadIdx.x;
    const int w    = tid >> 5;
    const int lane = tid & 31;

    float* s_l = (float*)(smem + SO_L);
    if (tid < BI) s_l[tid] = 0.f;

    // P-build mapping
    const int pi  = tid >> 3;          // 0..63
    const int pjq = tid & 7;           // 0..7 -> j offset pjq*4
    float4 ip = g_ip[r][i0 + pi];
    const float src_i = ip.x, E1 = ip.y, E2 = ip.z;
    float l_acc = 0.f;
    const int* arow = A + (size_t)(i0 + pi) * NN + pjq * 4;

    // Wh cp.async mapping: items tid and tid+512: d = idx>>2, piece = idx&3
    const int whd0 = tid >> 2, whp0 = tid & 3;
    const int whd1 = (tid + 512) >> 2, whp1 = (tid + 512) & 3;

    const int dwb = (w >> 1) * 32;
    const int nwb = (w & 1) * 32;

    // ldmatrix per-lane base offsets (bytes)
    const int ltile = lane >> 3, lwi = lane & 7;
    const uint32_t a_off =
        (uint32_t)(dwb + (ltile & 1) * 8 + lwi) * 80 + (ltile >> 1) * 16;
    const uint32_t b_off0 =
        (uint32_t)(nwb + ((ltile >> 1)) * 8 + lwi) * 80 + (ltile & 1) * 16;
    const uint32_t b_off1 =
        (uint32_t)(nwb + (2 + (ltile >> 1)) * 8 + lwi) * 80 + (ltile & 1) * 16;

    float c[2][4][4];
#pragma unroll
    for (int mi = 0; mi < 2; mi++)
#pragma unroll
        for (int ni = 0; ni < 4; ni++)
#pragma unroll
            for (int e = 0; e < 4; e++) c[mi][ni][e] = 0.f;

#define ISSUE_CHUNK(cc)                                                        \
    {                                                                          \
        const int j0_ = (cc) * BK;                                             \
        const int st_ = (cc) & 3;                                              \
        cp16(sb + SO_WH(st_) + whd0 * 80 + whp0 * 16,                          \
             WhT + (size_t)whd0 * NN + j0_ + whp0 * 8);                        \
        cp16(sb + SO_WH(st_) + whd1 * 80 + whp1 * 16,                          \
             WhT + (size_t)whd1 * NN + j0_ + whp1 * 8);                        \
        if (tid < 32) cp16(sb + SO_JP(st_) + tid * 16, jp + j0_ + tid);        \
        CP_COMMIT();                                                           \
    }

    // prologue: stages 0,1,2 in flight; A chunk 0 in regs
    ISSUE_CHUNK(0); ISSUE_CHUNK(1); ISSUE_CHUNK(2);
    int4 aa = *(const int4*)arow;

    for (int cch = 0; cch < NCH; cch++) {
        const int st = cch & 3;
        const int pb = cch & 1;
        CP_WAIT2();
        __syncthreads();   // stage-cch data visible; all warps done mma(cch-1)

        if (cch + 3 < NCH) ISSUE_CHUNK(cch + 3) else CP_COMMIT();

        int4 aan = aa;
        if (cch + 1 < NCH) aan = *(const int4*)(arow + (cch + 1) * BK);

        // ---- build P(cch) ----
        {
            int aav[4] = {aa.x, aa.y, aa.z, aa.w};
            __half hh[4];
#pragma unroll
            for (int e = 0; e < 4; e++) {
                float4 jv = *(const float4*)(smem + SO_JP(st) + pjq * 64 + e * 16);
                float s = src_i + jv.x;
                float p = (s > 0.f) ? (E1 * jv.y) : (E2 * jv.z);
                p = aav[e] ? p : 0.f;
                hh[e] = __float2half_rn(p);
                l_acc += __half2float(hh[e]);
            }
            uint2 pu;
            pu.x = (uint32_t)__half_as_ushort(hh[0]) |
                   ((uint32_t)__half_as_ushort(hh[1]) << 16);
            pu.y = (uint32_t)__half_as_ushort(hh[2]) |
                   ((uint32_t)__half_as_ushort(hh[3]) << 16);
            *(uint2*)(smem + SO_P(pb) + pi * 80 + pjq * 8) = pu;
        }
        aa = aan;
        __syncthreads();

        // ---- mma(cch) ----
        {
            const uint32_t whs = sb + SO_WH(st);
            const uint32_t ps  = sb + SO_P(pb);
#pragma unroll
            for (int kt = 0; kt < 2; kt++) {
                uint32_t af[2][4], bf[4][2];
                LDM4(af[0][0], af[0][1], af[0][2], af[0][3],
                     whs + a_off + kt * 32);
                LDM4(af[1][0], af[1][1], af[1][2], af[1][3],
                     whs + a_off + 1280 + kt * 32);
                LDM4(bf[0][0], bf[0][1], bf[1][0], bf[1][1],
                     ps + b_off0 + kt * 32);
                LDM4(bf[2][0], bf[2][1], bf[3][0], bf[3][1],
                     ps + b_off1 + kt * 32);
#pragma unroll
                for (int ni = 0; ni < 4; ni++)
#pragma unroll
                    for (int mi = 0; mi < 2; mi++) {
                        asm volatile(
                            "mma.sync.aligned.m16n8k16.row.col.f32.f16.f16.f32 "
                            "{%0,%1,%2,%3}, {%4,%5,%6,%7}, {%8,%9}, {%0,%1,%2,%3};"
                            : "+f"(c[mi][ni][0]), "+f"(c[mi][ni][1]),
                              "+f"(c[mi][ni][2]), "+f"(c[mi][ni][3])
                            : "r"(af[mi][0]), "r"(af[mi][1]),
                              "r"(af[mi][2]), "r"(af[mi][3]),
                              "r"(bf[ni][0]), "r"(bf[ni][1]));
                    }
            }
        }
    }

    // ---- row sums -> 1/l ----
    l_acc += __shfl_xor_sync(0xffffffffu, l_acc, 1);
    l_acc += __shfl_xor_sync(0xffffffffu, l_acc, 2);
    l_acc += __shfl_xor_sync(0xffffffffu, l_acc, 4);
    __syncthreads();
    if ((tid & 7) == 0) s_l[pi] = l_acc;
    __syncthreads();
    if (tid < BI) {
        float l = s_l[tid];
        s_l[tid] = (l > 0.f) ? (1.f / l) : 0.f;
    }
    __syncthreads();

    // ---- epilogue: scaled stores to transposed partials out3T[d][i] ----
    float* T = g_out3[r];
#pragma unroll
    for (int ni = 0; ni < 4; ni++) {
        int icol = nwb + ni * 8 + (lane & 3) * 2;
        float iv0 = s_l[icol];
        float iv1 = s_l[icol + 1];
#pragma unroll
        for (int mi = 0; mi < 2; mi++) {
            int d = dwb + mi * 16 + (lane >> 2);
            *(float2*)&T[(size_t)d * NN + i0 + icol] =
                make_float2(c[mi][ni][0] * iv0, c[mi][ni][1] * iv1);
            *(float2*)&T[(size_t)(d + 8) * NN + i0 + icol] =
                make_float2(c[mi][ni][2] * iv0, c[mi][ni][3] * iv1);
        }
    }
}

// ---------------------------------------------------------------------------
// Kernel 4: out[i][d] = sum_r out3T[r][d][i] + bias[d]
// ---------------------------------------------------------------------------
__global__ void __launch_bounds__(256) combine_t_kernel(
    const float* __restrict__ bias, float* __restrict__ out)
{
    const int i0 = blockIdx.x * 32;
    const int d0 = blockIdx.y * 32;
    __shared__ float t[32][33];

    const int tid = threadIdx.x;
    const int ty = tid >> 5;
    const int tx = tid & 31;

#pragma unroll
    for (int s = 0; s < 4; s++) {
        int dl = ty + s * 8;
        size_t off = (size_t)(d0 + dl) * NN + i0 + tx;
        t[dl][tx] = g_out3[0][off] + g_out3[1][off] + g_out3[2][off];
    }
    __syncthreads();

    const int il = tid >> 3;
    const int dq = (tid & 7) * 4;
    float4 b = *(const float4*)&bias[d0 + dq];
    float4 v;
    v.x = t[dq + 0][il] + b.x;
    v.y = t[dq + 1][il] + b.y;
    v.z = t[dq + 2][il] + b.z;
    v.w = t[dq + 3][il] + b.w;
    *(float4*)&out[(size_t)(i0 + il) * DD + d0 + dq] = v;
}

// ---------------------------------------------------------------------------
extern "C" void kernel_launch(void* const* d_in, const int* in_sizes, int n_in,
                              void* d_out, int out_size)
{
    const float* H    = (const float*)d_in[0];
    const float* W1   = (const float*)d_in[1];
    const float* W2   = (const float*)d_in[2];
    const float* W3   = (const float*)d_in[3];
    const float* a1   = (const float*)d_in[4];
    const float* a2   = (const float*)d_in[5];
    const float* a3   = (const float*)d_in[6];
    const float* bias = (const float*)d_in[7];
    const int*   A1   = (const int*)d_in[8];
    const int*   A2   = (const int*)d_in[9];
    const int*   A3   = (const int*)d_in[10];
    float* out = (float*)d_out;

    dim3 wh_grid(NN / 32, 3);
    wh_gemm_kernel<<<wh_grid, 256>>>(H, W1, W2, W3);

    dim3 tr_grid(NN / 32, DD / 32, 3);
    transpose_kernel<<<tr_grid, 256>>>();

    srcdst_kernel<<<3 * NN / 8, 256>>>(a1, a2, a3);

    cudaFuncSetAttribute(passb_mma_kernel,
                         cudaFuncAttributeMaxDynamicSharedMemorySize, SMEM_PB);
    dim3 pb_grid(NN / BI, 3);
    passb_mma_kernel<<<pb_grid, 512, SMEM_PB>>>(A1, A2, A3);

    dim3 cb_grid(NN / 32, DD / 32);
    combine_t_kernel<<<cb_grid, 256>>>(bias, out);
}